// round 5
// baseline (speedup 1.0000x reference)
#include <cuda_runtime.h>
#include <math.h>
#include <stdint.h>

// Problem dims
constexpr int BB = 8;
constexpr int SS = 1024;
constexpr int DD = 256;
constexpr int MTOT = BB * SS;          // 8192
constexpr int PAD = 32 * DD;

// Scratch (device globals — no cudaMalloc allowed)
__device__ float g_q[MTOT * DD + PAD];
__device__ float g_k[MTOT * DD + PAD];
__device__ float g_f[MTOT * DD + PAD];
__device__ float g_i[MTOT * DD + PAD];
__device__ float g_n[MTOT * DD];
__device__ float g_h[MTOT * DD];
__device__ float g_inv[MTOT + 64];

// ---- f32x2 helpers ----
__device__ __forceinline__ unsigned long long pack2(float lo, float hi) {
    unsigned long long r;
    asm("mov.b64 %0, {%1, %2};" : "=l"(r) : "f"(lo), "f"(hi));
    return r;
}
__device__ __forceinline__ unsigned long long fma2(
    unsigned long long a, unsigned long long b, unsigned long long c) {
    unsigned long long d;
    asm("fma.rn.f32x2 %0, %1, %2, %3;" : "=l"(d) : "l"(a), "l"(b), "l"(c));
    return d;
}
__device__ __forceinline__ unsigned long long mul2(
    unsigned long long a, unsigned long long b) {
    unsigned long long d;
    asm("mul.rn.f32x2 %0, %1, %2;" : "=l"(d) : "l"(a), "l"(b));
    return d;
}
__device__ __forceinline__ unsigned long long add2(
    unsigned long long a, unsigned long long b) {
    unsigned long long d;
    asm("add.rn.f32x2 %0, %1, %2;" : "=l"(d) : "l"(a), "l"(b));
    return d;
}
__device__ __forceinline__ void unpack2(unsigned long long v, float& lo, float& hi) {
    asm("mov.b64 {%0, %1}, %2;" : "=f"(lo), "=f"(hi) : "l"(v));
}

// ---- cp.async helpers ----
__device__ __forceinline__ void cp_async16(uint32_t saddr, const void* gptr) {
    asm volatile("cp.async.ca.shared.global [%0], [%1], 16;" :: "r"(saddr), "l"(gptr));
}
__device__ __forceinline__ void cp_async4(uint32_t saddr, const void* gptr) {
    asm volatile("cp.async.ca.shared.global [%0], [%1], 4;" :: "r"(saddr), "l"(gptr));
}
__device__ __forceinline__ void cp_commit() {
    asm volatile("cp.async.commit_group;");
}
template <int N>
__device__ __forceinline__ void cp_wait() {
    asm volatile("cp.async.wait_group %0;" :: "n"(N));
}

// ---------------------------------------------------------------------------
// GEMM: out[m,n] = act( sum_k A[m,k]*W[n,k] + bias[n] ).
// 128x128 tile, BK=8, 256 threads, 8x8 per thread, f32x2 FMA.
// ---------------------------------------------------------------------------
template <int ACT>
__global__ void __launch_bounds__(256) gemm_kernel(
    const float* __restrict__ A, const float* __restrict__ W,
    const float* __restrict__ bias, float* __restrict__ out)
{
    __shared__ float As[8][132];
    __shared__ float Bs[8][132];

    const int tid = threadIdx.x;
    const int m0 = blockIdx.y * 128;
    const int n0 = blockIdx.x * 128;
    const int lm = tid >> 1;
    const int lk = (tid & 1) << 2;
    const int tx = tid & 15;
    const int ty = tid >> 4;

    unsigned long long acc2[8][4] = {};

    float4 a4 = *(const float4*)(A + (size_t)(m0 + lm) * DD + lk);
    float4 w4 = *(const float4*)(W + (size_t)(n0 + lm) * DD + lk);

    for (int k0 = 0; k0 < DD; k0 += 8) {
        __syncthreads();
        As[lk + 0][lm] = a4.x; As[lk + 1][lm] = a4.y;
        As[lk + 2][lm] = a4.z; As[lk + 3][lm] = a4.w;
        Bs[lk + 0][lm] = w4.x; Bs[lk + 1][lm] = w4.y;
        Bs[lk + 2][lm] = w4.z; Bs[lk + 3][lm] = w4.w;
        __syncthreads();
        if (k0 + 8 < DD) {
            a4 = *(const float4*)(A + (size_t)(m0 + lm) * DD + k0 + 8 + lk);
            w4 = *(const float4*)(W + (size_t)(n0 + lm) * DD + k0 + 8 + lk);
        }
#pragma unroll
        for (int kk = 0; kk < 8; kk++) {
            float4 av0 = *(const float4*)&As[kk][ty * 8];
            float4 av1 = *(const float4*)&As[kk][ty * 8 + 4];
            float4 bv0 = *(const float4*)&Bs[kk][tx * 8];
            float4 bv1 = *(const float4*)&Bs[kk][tx * 8 + 4];
            unsigned long long b0 = pack2(bv0.x, bv0.y);
            unsigned long long b1 = pack2(bv0.z, bv0.w);
            unsigned long long b2 = pack2(bv1.x, bv1.y);
            unsigned long long b3 = pack2(bv1.z, bv1.w);
            float am[8] = {av0.x, av0.y, av0.z, av0.w, av1.x, av1.y, av1.z, av1.w};
#pragma unroll
            for (int i2 = 0; i2 < 8; i2++) {
                unsigned long long aa = pack2(am[i2], am[i2]);
                acc2[i2][0] = fma2(aa, b0, acc2[i2][0]);
                acc2[i2][1] = fma2(aa, b1, acc2[i2][1]);
                acc2[i2][2] = fma2(aa, b2, acc2[i2][2]);
                acc2[i2][3] = fma2(aa, b3, acc2[i2][3]);
            }
        }
    }

    float4 bb0 = *(const float4*)(bias + n0 + tx * 8);
    float4 bb1 = *(const float4*)(bias + n0 + tx * 8 + 4);
    float bb[8] = {bb0.x, bb0.y, bb0.z, bb0.w, bb1.x, bb1.y, bb1.z, bb1.w};
#pragma unroll
    for (int i2 = 0; i2 < 8; i2++) {
        float r[8];
        unpack2(acc2[i2][0], r[0], r[1]);
        unpack2(acc2[i2][1], r[2], r[3]);
        unpack2(acc2[i2][2], r[4], r[5]);
        unpack2(acc2[i2][3], r[6], r[7]);
        float4 o0, o1;
#pragma unroll
        for (int j2 = 0; j2 < 8; j2++) {
            float v = r[j2] + bb[j2];
            if (ACT == 1) v = 1.0f / (1.0f + expf(-v));
            else if (ACT == 2) v = expf(v);
            if (j2 < 4) (&o0.x)[j2] = v; else (&o1.x)[j2 - 4] = v;
        }
        float* dst = out + (size_t)(m0 + ty * 8 + i2) * DD + n0 + tx * 8;
        *(float4*)dst = o0;
        *(float4*)(dst + 4) = o1;
    }
}

// ---------------------------------------------------------------------------
// n-scan
// ---------------------------------------------------------------------------
__global__ void nscan_kernel()
{
    const int b = blockIdx.x >> 1;
    const int j = ((blockIdx.x & 1) << 7) + threadIdx.x;
    const size_t base = (size_t)b * SS * DD + j;
    float n = 0.0f;
#pragma unroll 8
    for (int t = 0; t < SS; t++) {
        size_t o = base + (size_t)t * DD;
        n = fmaf(g_f[o], n, g_i[o] * g_k[o]);
        g_n[o] = n;
    }
}

// ---------------------------------------------------------------------------
// den
// ---------------------------------------------------------------------------
__global__ void den_kernel()
{
    const int warp = threadIdx.x >> 5;
    const int lane = threadIdx.x & 31;
    const int m = blockIdx.x * 8 + warp;
    const size_t base = (size_t)m * DD + lane * 8;
    float4 na = *(const float4*)(g_n + base);
    float4 nb = *(const float4*)(g_n + base + 4);
    float4 qa = *(const float4*)(g_q + base);
    float4 qb = *(const float4*)(g_q + base + 4);
    float d = na.x * qa.x + na.y * qa.y + na.z * qa.z + na.w * qa.w
            + nb.x * qb.x + nb.y * qb.y + nb.z * qb.z + nb.w * qb.w;
#pragma unroll
    for (int o = 16; o; o >>= 1) d += __shfl_xor_sync(0xffffffffu, d, o);
    if (lane == 0) g_inv[m] = 1.0f / fmaxf(fabsf(d), 1.0f);
}

// ---------------------------------------------------------------------------
// Chunkwise C-scan. Chunk = 16 timesteps. CTA = 256 thr (8 warps), 16 rows.
// Per chunk:
//   A: G_t[i] = prod_{r<=t} f_r[i];  a_s[i] = i_s v_s / G_s     (16 threads)
//   B: P[t,s] = k_s.q_t (136 indep dots);  CQ[t,i] = C[i,:].q_t (256 indep
//      dots, C frozen);  then rank-16 C update + renorm C *= G_15
//   C: num_t[i] = G_t[i]*(CQ[t,i] + sum_{s<=t} a_s[i] P[t,s]); h = num*inv_den
// All dot/shuffle chains independent -> latency pipelined; only the
// once-per-chunk C update is serial.
// ---------------------------------------------------------------------------
constexpr int TC = 16;       // chunk length == stage size

struct CScanSmem {
    float k[2][TC][DD];      // 32 KB
    float q[2][TC][DD];      // 32 KB
    float g[2][TC][48];      // f[16] i[16] v[16] per t
    float d[2][TC];
    float G[TC][16];         // [t][row]
    float a[TC][16];         // [s][row]
    float P[TC][TC];         // [t][s]
    float CQ[TC][16];        // [t][row]
};
constexpr int CSMEM = sizeof(CScanSmem);

__global__ void __launch_bounds__(256, 1) cscan_kernel()
{
    extern __shared__ char smem_raw[];
    CScanSmem* S = (CScanSmem*)smem_raw;

    const int b    = blockIdx.x >> 4;
    const int grp  = blockIdx.x & 15;
    const int tid  = threadIdx.x;
    const int warp = tid >> 5;
    const int lane = tid & 31;
    const size_t mb = (size_t)b * SS * DD;
    const int rowb = grp * 16;
    const int r0 = warp * 2;             // warp's rows (r0, r0+1)

    const uint32_t sk_u = (uint32_t)__cvta_generic_to_shared(&S->k[0][0][0]);
    const uint32_t sq_u = (uint32_t)__cvta_generic_to_shared(&S->q[0][0][0]);
    const uint32_t sg_u = (uint32_t)__cvta_generic_to_shared(&S->g[0][0][0]);
    const uint32_t sd_u = (uint32_t)__cvta_generic_to_shared(&S->d[0][0]);

    auto fill = [&](int st, int tt) {
#pragma unroll
        for (int j = 0; j < 4; j++) {                // k: 1024 granules
            int idx = tid + j * 256;
            int t = idx >> 6, gr = idx & 63;
            cp_async16(sk_u + (uint32_t)(((st * TC + t) * DD + gr * 4) * 4),
                       g_k + mb + (size_t)(tt + t) * DD + gr * 4);
        }
#pragma unroll
        for (int j = 0; j < 4; j++) {                // q
            int idx = tid + j * 256;
            int t = idx >> 6, gr = idx & 63;
            cp_async16(sq_u + (uint32_t)(((st * TC + t) * DD + gr * 4) * 4),
                       g_q + mb + (size_t)(tt + t) * DD + gr * 4);
        }
        if (tid < 192) {                             // gates f,i,v (v == q)
            int t = tid / 12, gi = tid % 12;
            int gate = gi >> 2, part = gi & 3;
            const float* src =
                (gate == 0 ? g_f : (gate == 1 ? g_i : g_q))
                + mb + (size_t)(tt + t) * DD + rowb + part * 4;
            cp_async16(sg_u + (uint32_t)(((st * TC + t) * 48 + gate * 16 + part * 4) * 4),
                       src);
        }
        if (tid < TC)
            cp_async4(sd_u + (uint32_t)((st * TC + tid) * 4),
                      g_inv + b * SS + tt + tid);
    };

    // state: warp's 2 rows x 8 cols (as f32x2 pairs); lane cols {4L..4L+3, 128+4L..}
    unsigned long long C2[2][4];
#pragma unroll
    for (int r = 0; r < 2; r++)
#pragma unroll
        for (int c = 0; c < 4; c++) C2[r][c] = 0ull;

    fill(0, 0); cp_commit();
    fill(1, TC); cp_commit();

    for (int blk = 0; blk < SS / TC; blk++) {
        const int st = blk & 1;
        cp_wait<1>();
        __syncthreads();

        // ---- Phase A: gate prefix products (16 threads) ----
        if (tid < 16) {
            float g = 1.0f;
#pragma unroll
            for (int t = 0; t < TC; t++) {
                float f = S->g[st][t][tid];
                float ig = S->g[st][t][16 + tid];
                float vg = S->g[st][t][32 + tid];
                g *= f;
                S->G[t][tid] = g;
                S->a[t][tid] = __fdividef(ig * vg, g);
            }
        }
        __syncthreads();

        // ---- Phase B ----
        // P[t][s] = k_s . q_t  (136 pairs, 17 per warp)
#pragma unroll
        for (int j = 0; j < 17; j++) {
            int pp = warp + j * 8;
            int t = (int)((sqrtf(8.0f * (float)pp + 1.0f) - 1.0f) * 0.5f);
            if ((t + 1) * (t + 2) / 2 <= pp) t++;
            if (t * (t + 1) / 2 > pp) t--;
            int s = pp - t * (t + 1) / 2;
            const float4 Ka = *(const float4*)&S->k[st][s][lane * 4];
            const float4 Kb = *(const float4*)&S->k[st][s][128 + lane * 4];
            const float4 Qa = *(const float4*)&S->q[st][t][lane * 4];
            const float4 Qb = *(const float4*)&S->q[st][t][128 + lane * 4];
            float p = Ka.x * Qa.x + Ka.y * Qa.y + Ka.z * Qa.z + Ka.w * Qa.w
                    + Kb.x * Qb.x + Kb.y * Qb.y + Kb.z * Qb.z + Kb.w * Qb.w;
#pragma unroll
            for (int o = 16; o; o >>= 1) p += __shfl_xor_sync(0xffffffffu, p, o);
            if (lane == 0) S->P[t][s] = p;
        }

        // CQ[t][r] = C[r,:].q_t  (C frozen for whole chunk; 32 dots/warp)
#pragma unroll
        for (int t = 0; t < TC; t++) {
            const float4 Qa = *(const float4*)&S->q[st][t][lane * 4];
            const float4 Qb = *(const float4*)&S->q[st][t][128 + lane * 4];
            unsigned long long q2[4] = {pack2(Qa.x, Qa.y), pack2(Qa.z, Qa.w),
                                        pack2(Qb.x, Qb.y), pack2(Qb.z, Qb.w)};
            float res[2];
#pragma unroll
            for (int r = 0; r < 2; r++) {
                unsigned long long d0 = mul2(C2[r][0], q2[0]);
                unsigned long long d1 = mul2(C2[r][1], q2[1]);
                d0 = fma2(C2[r][2], q2[2], d0);
                d1 = fma2(C2[r][3], q2[3], d1);
                unsigned long long sres = add2(d0, d1);
                float lo, hi; unpack2(sres, lo, hi);
                res[r] = lo + hi;
            }
#pragma unroll
            for (int o = 16; o; o >>= 1) {
                res[0] += __shfl_xor_sync(0xffffffffu, res[0], o);
                res[1] += __shfl_xor_sync(0xffffffffu, res[1], o);
            }
            if (lane == 0) {
                S->CQ[t][r0] = res[0];
                S->CQ[t][r0 + 1] = res[1];
            }
        }

        // rank-16 C update: C[r,:] += sum_s a_s[r] k_s
#pragma unroll
        for (int s = 0; s < TC; s++) {
            const float4 Ka = *(const float4*)&S->k[st][s][lane * 4];
            const float4 Kb = *(const float4*)&S->k[st][s][128 + lane * 4];
            unsigned long long k2[4] = {pack2(Ka.x, Ka.y), pack2(Ka.z, Ka.w),
                                        pack2(Kb.x, Kb.y), pack2(Kb.z, Kb.w)};
            float a0 = S->a[s][r0];
            float a1 = S->a[s][r0 + 1];
            unsigned long long a02 = pack2(a0, a0);
            unsigned long long a12 = pack2(a1, a1);
#pragma unroll
            for (int c = 0; c < 4; c++) {
                C2[0][c] = fma2(a02, k2[c], C2[0][c]);
                C2[1][c] = fma2(a12, k2[c], C2[1][c]);
            }
        }
        // renorm: C *= G_end
        {
            float g0 = S->G[TC - 1][r0];
            float g1 = S->G[TC - 1][r0 + 1];
            unsigned long long g02 = pack2(g0, g0);
            unsigned long long g12 = pack2(g1, g1);
#pragma unroll
            for (int c = 0; c < 4; c++) {
                C2[0][c] = mul2(C2[0][c], g02);
                C2[1][c] = mul2(C2[1][c], g12);
            }
        }
        __syncthreads();

        // ---- Phase C: combine + store (thread = (t, row)) ----
        {
            const int t = tid >> 4;
            const int i = tid & 15;
            float num = S->CQ[t][i];
            for (int s = 0; s <= t; s++)
                num = fmaf(S->a[s][i], S->P[t][s], num);
            float h = S->G[t][i] * num * S->d[st][t];
            g_h[mb + (size_t)(blk * TC + t) * DD + rowb + i] = h;
        }
        __syncthreads();

        const int nb = blk + 2;
        if (nb < SS / TC) fill(st, nb * TC);
        cp_commit();
    }
}

// ---------------------------------------------------------------------------
// Launch
// ---------------------------------------------------------------------------
extern "C" void kernel_launch(void* const* d_in, const int* in_sizes, int n_in,
                              void* d_out, int out_size)
{
    const float* x   = (const float*)d_in[0];
    const float* Wq  = (const float*)d_in[1];
    const float* bq  = (const float*)d_in[2];
    const float* Wk  = (const float*)d_in[3];
    const float* bkk = (const float*)d_in[4];
    // d_in[5] = Wv, d_in[6] = bv — unused (reference uses W_q for v)
    const float* Wf  = (const float*)d_in[7];
    const float* bff = (const float*)d_in[8];
    const float* Wi  = (const float*)d_in[9];
    const float* bii = (const float*)d_in[10];
    const float* Wo  = (const float*)d_in[11];
    const float* bo  = (const float*)d_in[12];
    float* out = (float*)d_out;

    float *pq, *pk, *pf, *pi, *ph;
    cudaGetSymbolAddress((void**)&pq, g_q);
    cudaGetSymbolAddress((void**)&pk, g_k);
    cudaGetSymbolAddress((void**)&pf, g_f);
    cudaGetSymbolAddress((void**)&pi, g_i);
    cudaGetSymbolAddress((void**)&ph, g_h);

    static int smem_set = 0;
    if (!smem_set) {
        cudaFuncSetAttribute(cscan_kernel,
                             cudaFuncAttributeMaxDynamicSharedMemorySize, CSMEM);
        smem_set = 1;
    }

    dim3 ggrid(DD / 128, MTOT / 128);   // (2, 64) = 128 CTAs

    gemm_kernel<0><<<ggrid, 256>>>(x, Wq, bq, pq);
    gemm_kernel<0><<<ggrid, 256>>>(x, Wk, bkk, pk);
    gemm_kernel<1><<<ggrid, 256>>>(x, Wf, bff, pf);
    gemm_kernel<2><<<ggrid, 256>>>(x, Wi, bii, pi);

    nscan_kernel<<<16, 128>>>();
    den_kernel<<<MTOT / 8, 256>>>();
    cscan_kernel<<<BB * 16, 256, CSMEM>>>();

    gemm_kernel<0><<<ggrid, 256>>>(ph, Wo, bo, out);
}

// round 6
// speedup vs baseline: 1.1372x; 1.1372x over previous
#include <cuda_runtime.h>
#include <math.h>
#include <stdint.h>

// Problem dims
constexpr int BB = 8;
constexpr int SS = 1024;
constexpr int DD = 256;
constexpr int MTOT = BB * SS;          // 8192
constexpr int PAD = 32 * DD;

// Scratch (device globals — no cudaMalloc allowed)
__device__ float g_q[MTOT * DD + PAD];
__device__ float g_k[MTOT * DD + PAD];
__device__ float g_f[MTOT * DD + PAD];
__device__ float g_i[MTOT * DD + PAD];
__device__ float g_n[MTOT * DD];
__device__ float g_h[MTOT * DD];
__device__ float g_inv[MTOT + 64];

typedef unsigned long long ull;

// ---- f32x2 helpers ----
__device__ __forceinline__ ull pack2(float lo, float hi) {
    ull r; asm("mov.b64 %0, {%1, %2};" : "=l"(r) : "f"(lo), "f"(hi)); return r;
}
__device__ __forceinline__ ull fma2(ull a, ull b, ull c) {
    ull d; asm("fma.rn.f32x2 %0, %1, %2, %3;" : "=l"(d) : "l"(a), "l"(b), "l"(c)); return d;
}
__device__ __forceinline__ ull mul2(ull a, ull b) {
    ull d; asm("mul.rn.f32x2 %0, %1, %2;" : "=l"(d) : "l"(a), "l"(b)); return d;
}
__device__ __forceinline__ ull add2(ull a, ull b) {
    ull d; asm("add.rn.f32x2 %0, %1, %2;" : "=l"(d) : "l"(a), "l"(b)); return d;
}
__device__ __forceinline__ void unpack2(ull v, float& lo, float& hi) {
    asm("mov.b64 {%0, %1}, %2;" : "=f"(lo), "=f"(hi) : "l"(v));
}

// ---- cp.async helpers ----
__device__ __forceinline__ void cp_async16(uint32_t saddr, const void* gptr) {
    asm volatile("cp.async.ca.shared.global [%0], [%1], 16;" :: "r"(saddr), "l"(gptr));
}
__device__ __forceinline__ void cp_async4(uint32_t saddr, const void* gptr) {
    asm volatile("cp.async.ca.shared.global [%0], [%1], 4;" :: "r"(saddr), "l"(gptr));
}
__device__ __forceinline__ void cp_commit() { asm volatile("cp.async.commit_group;"); }
template <int N>
__device__ __forceinline__ void cp_wait() {
    asm volatile("cp.async.wait_group %0;" :: "n"(N));
}

// ---------------------------------------------------------------------------
// GEMM (unchanged from R4): 128x128 tile, BK=8, 256 thr, 8x8/thread, f32x2.
// ---------------------------------------------------------------------------
template <int ACT>
__global__ void __launch_bounds__(256) gemm_kernel(
    const float* __restrict__ A, const float* __restrict__ W,
    const float* __restrict__ bias, float* __restrict__ out)
{
    __shared__ float As[8][132];
    __shared__ float Bs[8][132];

    const int tid = threadIdx.x;
    const int m0 = blockIdx.y * 128;
    const int n0 = blockIdx.x * 128;
    const int lm = tid >> 1;
    const int lk = (tid & 1) << 2;
    const int tx = tid & 15;
    const int ty = tid >> 4;

    ull acc2[8][4] = {};

    float4 a4 = *(const float4*)(A + (size_t)(m0 + lm) * DD + lk);
    float4 w4 = *(const float4*)(W + (size_t)(n0 + lm) * DD + lk);

    for (int k0 = 0; k0 < DD; k0 += 8) {
        __syncthreads();
        As[lk + 0][lm] = a4.x; As[lk + 1][lm] = a4.y;
        As[lk + 2][lm] = a4.z; As[lk + 3][lm] = a4.w;
        Bs[lk + 0][lm] = w4.x; Bs[lk + 1][lm] = w4.y;
        Bs[lk + 2][lm] = w4.z; Bs[lk + 3][lm] = w4.w;
        __syncthreads();
        if (k0 + 8 < DD) {
            a4 = *(const float4*)(A + (size_t)(m0 + lm) * DD + k0 + 8 + lk);
            w4 = *(const float4*)(W + (size_t)(n0 + lm) * DD + k0 + 8 + lk);
        }
#pragma unroll
        for (int kk = 0; kk < 8; kk++) {
            float4 av0 = *(const float4*)&As[kk][ty * 8];
            float4 av1 = *(const float4*)&As[kk][ty * 8 + 4];
            float4 bv0 = *(const float4*)&Bs[kk][tx * 8];
            float4 bv1 = *(const float4*)&Bs[kk][tx * 8 + 4];
            ull b0 = pack2(bv0.x, bv0.y);
            ull b1 = pack2(bv0.z, bv0.w);
            ull b2 = pack2(bv1.x, bv1.y);
            ull b3 = pack2(bv1.z, bv1.w);
            float am[8] = {av0.x, av0.y, av0.z, av0.w, av1.x, av1.y, av1.z, av1.w};
#pragma unroll
            for (int i2 = 0; i2 < 8; i2++) {
                ull aa = pack2(am[i2], am[i2]);
                acc2[i2][0] = fma2(aa, b0, acc2[i2][0]);
                acc2[i2][1] = fma2(aa, b1, acc2[i2][1]);
                acc2[i2][2] = fma2(aa, b2, acc2[i2][2]);
                acc2[i2][3] = fma2(aa, b3, acc2[i2][3]);
            }
        }
    }

    float4 bb0 = *(const float4*)(bias + n0 + tx * 8);
    float4 bb1 = *(const float4*)(bias + n0 + tx * 8 + 4);
    float bb[8] = {bb0.x, bb0.y, bb0.z, bb0.w, bb1.x, bb1.y, bb1.z, bb1.w};
#pragma unroll
    for (int i2 = 0; i2 < 8; i2++) {
        float r[8];
        unpack2(acc2[i2][0], r[0], r[1]);
        unpack2(acc2[i2][1], r[2], r[3]);
        unpack2(acc2[i2][2], r[4], r[5]);
        unpack2(acc2[i2][3], r[6], r[7]);
        float4 o0, o1;
#pragma unroll
        for (int j2 = 0; j2 < 8; j2++) {
            float v = r[j2] + bb[j2];
            if (ACT == 1) v = 1.0f / (1.0f + expf(-v));
            else if (ACT == 2) v = expf(v);
            if (j2 < 4) (&o0.x)[j2] = v; else (&o1.x)[j2 - 4] = v;
        }
        float* dst = out + (size_t)(m0 + ty * 8 + i2) * DD + n0 + tx * 8;
        *(float4*)dst = o0;
        *(float4*)(dst + 4) = o1;
    }
}

// ---------------------------------------------------------------------------
// n-scan
// ---------------------------------------------------------------------------
__global__ void nscan_kernel()
{
    const int b = blockIdx.x >> 1;
    const int j = ((blockIdx.x & 1) << 7) + threadIdx.x;
    const size_t base = (size_t)b * SS * DD + j;
    float n = 0.0f;
#pragma unroll 8
    for (int t = 0; t < SS; t++) {
        size_t o = base + (size_t)t * DD;
        n = fmaf(g_f[o], n, g_i[o] * g_k[o]);
        g_n[o] = n;
    }
}

// ---------------------------------------------------------------------------
// den
// ---------------------------------------------------------------------------
__global__ void den_kernel()
{
    const int warp = threadIdx.x >> 5;
    const int lane = threadIdx.x & 31;
    const int m = blockIdx.x * 8 + warp;
    const size_t base = (size_t)m * DD + lane * 8;
    float4 na = *(const float4*)(g_n + base);
    float4 nb = *(const float4*)(g_n + base + 4);
    float4 qa = *(const float4*)(g_q + base);
    float4 qb = *(const float4*)(g_q + base + 4);
    float d = na.x * qa.x + na.y * qa.y + na.z * qa.z + na.w * qa.w
            + nb.x * qb.x + nb.y * qb.y + nb.z * qb.z + nb.w * qb.w;
#pragma unroll
    for (int o = 16; o; o >>= 1) d += __shfl_xor_sync(0xffffffffu, d, o);
    if (lane == 0) g_inv[m] = 1.0f / fmaxf(fabsf(d), 1.0f);
}

// ---------------------------------------------------------------------------
// Chunkwise C-scan, SHUFFLE-FREE. Chunk=16 steps, CTA=256 thr, 16 rows.
// C state lives in SMEM [16][260] (stride 260 => conflict-free; 260%32==4).
// Per chunk:
//   A (16 thr):   G[u][i]=prod f;  a[u][i]=i*v/G
//   dots:         thread (t,j): P[t][j]=k_j.q_t  AND  CQ[t][j]=C[j,:].q_t
//                 (fused k-loop, thread-private accumulators, NO reductions)
//   update:       thread (i,j): C[i][cols 4j+64m] += sum_s a[s][i]*k_s; *=G15
//   combine:      thread (t,i): h = G[t][i]*(CQ+sum_{s<=t} a[s][i]P[t][s])*inv
// ---------------------------------------------------------------------------
constexpr int TC = 16;
constexpr int LDR = 260;           // padded row stride (floats)

struct CScanSmem {
    float k[2][TC][LDR];           // 33.3 KB
    float q[2][TC][LDR];           // 33.3 KB
    float C[TC][LDR];              // 16.6 KB
    float g[2][TC][48];            // f[16] i[16] v[16]
    float d[2][TC];
    float G[TC][16];               // [u][row]
    float a[TC][16];               // [u][row]
    float P[TC][TC];               // [t][s]
    float CQ[TC][16];              // [t][row]
};
constexpr int CSMEM = sizeof(CScanSmem);

__global__ void __launch_bounds__(256, 1) cscan_kernel()
{
    extern __shared__ char smem_raw[];
    CScanSmem* S = (CScanSmem*)smem_raw;

    const int b    = blockIdx.x >> 4;
    const int grp  = blockIdx.x & 15;
    const int tid  = threadIdx.x;
    const size_t mb = (size_t)b * SS * DD;
    const int rowb = grp * 16;

    const uint32_t sk_u = (uint32_t)__cvta_generic_to_shared(&S->k[0][0][0]);
    const uint32_t sq_u = (uint32_t)__cvta_generic_to_shared(&S->q[0][0][0]);
    const uint32_t sg_u = (uint32_t)__cvta_generic_to_shared(&S->g[0][0][0]);
    const uint32_t sd_u = (uint32_t)__cvta_generic_to_shared(&S->d[0][0]);

    auto fill = [&](int st, int tt) {
#pragma unroll
        for (int j = 0; j < 4; j++) {                // k: 1024 16B granules
            int idx = tid + j * 256;
            int t = idx >> 6, gr = idx & 63;
            cp_async16(sk_u + (uint32_t)(((st * TC + t) * LDR + gr * 4) * 4),
                       g_k + mb + (size_t)(tt + t) * DD + gr * 4);
        }
#pragma unroll
        for (int j = 0; j < 4; j++) {                // q
            int idx = tid + j * 256;
            int t = idx >> 6, gr = idx & 63;
            cp_async16(sq_u + (uint32_t)(((st * TC + t) * LDR + gr * 4) * 4),
                       g_q + mb + (size_t)(tt + t) * DD + gr * 4);
        }
        if (tid < 192) {                             // gates f,i,v (v == q)
            int t = tid / 12, gi = tid % 12;
            int gate = gi >> 2, part = gi & 3;
            const float* src =
                (gate == 0 ? g_f : (gate == 1 ? g_i : g_q))
                + mb + (size_t)(tt + t) * DD + rowb + part * 4;
            cp_async16(sg_u + (uint32_t)(((st * TC + t) * 48 + gate * 16 + part * 4) * 4),
                       src);
        }
        if (tid < TC)
            cp_async4(sd_u + (uint32_t)((st * TC + tid) * 4),
                      g_inv + b * SS + tt + tid);
    };

    // zero C
    for (int idx = tid; idx < TC * LDR; idx += 256)
        (&S->C[0][0])[idx] = 0.0f;

    fill(0, 0); cp_commit();
    fill(1, TC); cp_commit();

    for (int blk = 0; blk < SS / TC; blk++) {
        const int st = blk & 1;
        cp_wait<1>();
        __syncthreads();

        // ---- Phase A: gate prefix products (16 threads) ----
        if (tid < 16) {
            float g = 1.0f;
#pragma unroll
            for (int u = 0; u < TC; u++) {
                float f  = S->g[st][u][tid];
                float ig = S->g[st][u][16 + tid];
                float vg = S->g[st][u][32 + tid];
                g *= f;
                S->G[u][tid] = g;
                S->a[u][tid] = __fdividef(ig * vg, g);
            }
        }
        __syncthreads();

        // ---- dots: P[t][j] and CQ[t][j], thread-private, no reductions ----
        {
            const int t = tid >> 4, j = tid & 15;
            const float* qrow = &S->q[st][t][0];
            const float* krow = &S->k[st][j][0];
            const float* Crow = &S->C[j][0];
            ull accP0 = 0, accP1 = 0, accQ0 = 0, accQ1 = 0;
#pragma unroll 8
            for (int c = 0; c < DD; c += 4) {
                float4 q4 = *(const float4*)(qrow + c);
                float4 k4 = *(const float4*)(krow + c);
                float4 C4 = *(const float4*)(Crow + c);
                ull q01 = pack2(q4.x, q4.y), q23 = pack2(q4.z, q4.w);
                accP0 = fma2(q01, pack2(k4.x, k4.y), accP0);
                accP1 = fma2(q23, pack2(k4.z, k4.w), accP1);
                accQ0 = fma2(q01, pack2(C4.x, C4.y), accQ0);
                accQ1 = fma2(q23, pack2(C4.z, C4.w), accQ1);
            }
            float l, h;
            unpack2(add2(accP0, accP1), l, h);
            S->P[t][j] = l + h;
            unpack2(add2(accQ0, accQ1), l, h);
            S->CQ[t][j] = l + h;
        }
        __syncthreads();   // dots read C; update writes C

        // ---- update: C[i][:] += sum_s a[s][i] k_s ; C *= G15[i] ----
        {
            const int i = tid >> 4, j = tid & 15;
            ull acc[4][2];
#pragma unroll
            for (int m = 0; m < 4; m++) {
                float4 c4 = *(const float4*)&S->C[i][4 * j + 64 * m];
                acc[m][0] = pack2(c4.x, c4.y);
                acc[m][1] = pack2(c4.z, c4.w);
            }
#pragma unroll 4
            for (int s = 0; s < TC; s++) {
                float as = S->a[s][i];
                ull as2 = pack2(as, as);
#pragma unroll
                for (int m = 0; m < 4; m++) {
                    float4 k4 = *(const float4*)&S->k[st][s][4 * j + 64 * m];
                    acc[m][0] = fma2(as2, pack2(k4.x, k4.y), acc[m][0]);
                    acc[m][1] = fma2(as2, pack2(k4.z, k4.w), acc[m][1]);
                }
            }
            float ge = S->G[TC - 1][i];
            ull g2 = pack2(ge, ge);
#pragma unroll
            for (int m = 0; m < 4; m++) {
                float4 c4;
                unpack2(mul2(acc[m][0], g2), c4.x, c4.y);
                unpack2(mul2(acc[m][1], g2), c4.z, c4.w);
                *(float4*)&S->C[i][4 * j + 64 * m] = c4;
            }
        }

        // ---- combine + store (runs concurrently with update; disjoint data) ----
        {
            const int t = tid >> 4, i = tid & 15;
            float num = S->CQ[t][i];
            for (int s = 0; s <= t; s++)
                num = fmaf(S->a[s][i], S->P[t][s], num);
            float h = S->G[t][i] * num * S->d[st][t];
            g_h[mb + (size_t)(blk * TC + t) * DD + rowb + i] = h;
        }
        __syncthreads();   // all reads of stage st done -> safe to refill

        const int nb = blk + 2;
        if (nb < SS / TC) fill(st, nb * TC);
        cp_commit();
    }
}

// ---------------------------------------------------------------------------
// Launch
// ---------------------------------------------------------------------------
extern "C" void kernel_launch(void* const* d_in, const int* in_sizes, int n_in,
                              void* d_out, int out_size)
{
    const float* x   = (const float*)d_in[0];
    const float* Wq  = (const float*)d_in[1];
    const float* bq  = (const float*)d_in[2];
    const float* Wk  = (const float*)d_in[3];
    const float* bkk = (const float*)d_in[4];
    // d_in[5] = Wv, d_in[6] = bv — unused (reference uses W_q for v)
    const float* Wf  = (const float*)d_in[7];
    const float* bff = (const float*)d_in[8];
    const float* Wi  = (const float*)d_in[9];
    const float* bii = (const float*)d_in[10];
    const float* Wo  = (const float*)d_in[11];
    const float* bo  = (const float*)d_in[12];
    float* out = (float*)d_out;

    float *pq, *pk, *pf, *pi, *ph;
    cudaGetSymbolAddress((void**)&pq, g_q);
    cudaGetSymbolAddress((void**)&pk, g_k);
    cudaGetSymbolAddress((void**)&pf, g_f);
    cudaGetSymbolAddress((void**)&pi, g_i);
    cudaGetSymbolAddress((void**)&ph, g_h);

    static int smem_set = 0;
    if (!smem_set) {
        cudaFuncSetAttribute(cscan_kernel,
                             cudaFuncAttributeMaxDynamicSharedMemorySize, CSMEM);
        smem_set = 1;
    }

    dim3 ggrid(DD / 128, MTOT / 128);   // (2, 64) = 128 CTAs

    gemm_kernel<0><<<ggrid, 256>>>(x, Wq, bq, pq);
    gemm_kernel<0><<<ggrid, 256>>>(x, Wk, bkk, pk);
    gemm_kernel<1><<<ggrid, 256>>>(x, Wf, bff, pf);
    gemm_kernel<2><<<ggrid, 256>>>(x, Wi, bii, pi);

    nscan_kernel<<<16, 128>>>();
    den_kernel<<<MTOT / 8, 256>>>();
    cscan_kernel<<<BB * 16, 256, CSMEM>>>();

    gemm_kernel<0><<<ggrid, 256>>>(ph, Wo, bo, out);
}